// round 2
// baseline (speedup 1.0000x reference)
#include <cuda_runtime.h>
#include <math.h>

#define NN 100000
#define NE 1600000
#define ETOT (NE + NN)
#define D 128
#define H 64

// ---------------- scratch (device globals; no allocation allowed) ----------
__device__ float g_h[NN * H];      // node features between stages
__device__ float g_z[NN * H];      // z = h @ W per layer
__device__ float g_hnew[NN * H];   // GAT aggregation target
__device__ float g_zs[NN];
__device__ float g_zd[NN];
__device__ float g_m[NN];          // segment max
__device__ float g_denom[NN];      // softmax denom
__device__ float g_e[ETOT];        // per-edge logit, then exp
__device__ float g_deg[NN];
__device__ float g_infl[NN];
__device__ unsigned int g_stat[2]; // [0]=deg max bits, [1]=infl max bits

// ---------------- helpers ----------------
__device__ __forceinline__ void atomicMaxF(float* addr, float val) {
    if (val >= 0.f) atomicMax((int*)addr, __float_as_int(val));
    else            atomicMin((unsigned int*)addr, __float_as_uint(val));
}

// ---------------- K0: feature attention + projection --------------------
// block = 64 threads, one node per block
__global__ void k_feat(const float* __restrict__ x,
                       const float* __restrict__ W1, const float* __restrict__ b1,
                       const float* __restrict__ W2, const float* __restrict__ b2,
                       const float* __restrict__ Wp, const float* __restrict__ bp) {
    int node = blockIdx.x;
    int t = threadIdx.x;
    __shared__ float sx[D], st[H], sxf[D];
    sx[t]      = x[(size_t)node * D + t];
    sx[t + 64] = x[(size_t)node * D + t + 64];
    __syncthreads();

    float acc = b1[t];
#pragma unroll 8
    for (int k = 0; k < D; k++) acc = fmaf(sx[k], W1[k * H + t], acc);
    st[t] = fmaxf(acc, 0.f);
    __syncthreads();

#pragma unroll
    for (int r = 0; r < 2; r++) {
        int i = t + r * 64;
        float a = b2[i];
#pragma unroll 8
        for (int j = 0; j < H; j++) a = fmaf(st[j], W2[j * D + i], a);
        sxf[i] = sx[i] / (1.f + expf(-a));   // x * sigmoid(a)
    }
    __syncthreads();

    float hacc = bp[t];
#pragma unroll 8
    for (int k = 0; k < D; k++) hacc = fmaf(sxf[k], Wp[k * H + t], hacc);
    g_h[(size_t)node * H + t] = hacc;
}

// ---------------- K1: z = h @ W, zs = z.a_src, zd = z.a_dst -------------
__global__ void k_zproj(const float* __restrict__ W,
                        const float* __restrict__ asrc,
                        const float* __restrict__ adst) {
    int node = blockIdx.x;
    int t = threadIdx.x;
    __shared__ float sh[H], r1[H], r2[H];
    sh[t] = g_h[(size_t)node * H + t];
    __syncthreads();

    float acc = 0.f;
#pragma unroll
    for (int k = 0; k < H; k++) acc = fmaf(sh[k], W[k * H + t], acc);
    g_z[(size_t)node * H + t] = acc;
    r1[t] = acc * asrc[t];
    r2[t] = acc * adst[t];
    __syncthreads();
#pragma unroll
    for (int s = 32; s > 0; s >>= 1) {
        if (t < s) { r1[t] += r1[t + s]; r2[t] += r2[t + s]; }
        __syncthreads();
    }
    if (t == 0) { g_zs[node] = r1[0]; g_zd[node] = r2[0]; }
}

// ---------------- K2: per-layer init ----------------
__global__ void k_init() {
    int i = blockIdx.x * blockDim.x + threadIdx.x;
    if (i < NN * H) g_hnew[i] = 0.f;
    if (i < NN) { g_m[i] = __int_as_float(0xff800000); g_denom[i] = 0.f; }
}

// ---------------- K3: edge logits + segment max ----------------
__global__ void k_edge_max(const int* __restrict__ src, const int* __restrict__ dst) {
    int i = blockIdx.x * blockDim.x + threadIdx.x;
    if (i >= ETOT) return;
    int s, d;
    if (i < NE) { s = src[i]; d = dst[i]; }
    else        { s = d = i - NE; }
    float e = g_zs[s] + g_zd[d];
    e = (e > 0.f) ? e : 0.2f * e;   // leaky_relu(., 0.2)
    g_e[i] = e;
    atomicMaxF(&g_m[d], e);
}

// ---------------- K4: exp + segment sum ----------------
__global__ void k_edge_exp(const int* __restrict__ dst) {
    int i = blockIdx.x * blockDim.x + threadIdx.x;
    if (i >= ETOT) return;
    int d = (i < NE) ? dst[i] : (i - NE);
    float ex = expf(g_e[i] - g_m[d]);
    g_e[i] = ex;
    atomicAdd(&g_denom[d], ex);
}

// ---------------- K5: weighted scatter-add (warp per edge) ----------------
__global__ void k_edge_agg(const int* __restrict__ src, const int* __restrict__ dst) {
    long long gid = (long long)blockIdx.x * blockDim.x + threadIdx.x;
    long long w = gid >> 5;
    int lane = threadIdx.x & 31;
    if (w >= ETOT) return;
    int s, d;
    if (w < NE) { s = src[w]; d = dst[w]; }
    else        { s = d = (int)(w - NE); }
    float alpha = g_e[w] / g_denom[d];
    const float* zr = g_z + (size_t)s * H;
    float* hr = g_hnew + (size_t)d * H;
    atomicAdd(hr + lane,      zr[lane]      * alpha);
    atomicAdd(hr + lane + 32, zr[lane + 32] * alpha);
}

// ---------------- K6: bias + batchnorm + relu ----------------
__global__ void k_bn(const float* __restrict__ b, const float* __restrict__ gamma,
                     const float* __restrict__ beta, const float* __restrict__ mean,
                     const float* __restrict__ var) {
    int i = blockIdx.x * blockDim.x + threadIdx.x;
    if (i >= NN * H) return;
    int j = i & (H - 1);
    float v = g_hnew[i] + b[j];
    v = (v - mean[j]) * rsqrtf(var[j] + 1e-5f) * gamma[j] + beta[j];
    g_h[i] = fmaxf(v, 0.f);
}

// ---------------- structural features ----------------
__global__ void k_szero() {
    int i = blockIdx.x * blockDim.x + threadIdx.x;
    if (i < NN) { g_deg[i] = 0.f; g_infl[i] = 0.f; }
    if (i < 2) g_stat[i] = 0u;
}
__global__ void k_deg(const int* __restrict__ src) {
    int i = blockIdx.x * blockDim.x + threadIdx.x;
    if (i < NE) atomicAdd(&g_deg[src[i]], 1.f);
}
__global__ void k_degmax() {
    __shared__ float sm[256];
    int i = blockIdx.x * 256 + threadIdx.x;
    float v = (i < NN) ? g_deg[i] : 0.f;
    sm[threadIdx.x] = v;
    __syncthreads();
    for (int s = 128; s > 0; s >>= 1) {
        if (threadIdx.x < s) sm[threadIdx.x] = fmaxf(sm[threadIdx.x], sm[threadIdx.x + s]);
        __syncthreads();
    }
    if (threadIdx.x == 0) atomicMax(&g_stat[0], __float_as_uint(sm[0]));
}
__global__ void k_infl(const int* __restrict__ src, const int* __restrict__ dst) {
    int i = blockIdx.x * blockDim.x + threadIdx.x;
    if (i < NE) atomicAdd(&g_infl[src[i]], g_deg[dst[i]]);
}
__global__ void k_inflnorm() {
    __shared__ float sm[256];
    int i = blockIdx.x * 256 + threadIdx.x;
    float v = 0.f;
    if (i < NN) {
        float dg = g_deg[i];
        v = (dg > 0.f) ? g_infl[i] / fmaxf(dg, 1.f) : 0.f;
        g_infl[i] = v;
    }
    sm[threadIdx.x] = v;
    __syncthreads();
    for (int s = 128; s > 0; s >>= 1) {
        if (threadIdx.x < s) sm[threadIdx.x] = fmaxf(sm[threadIdx.x], sm[threadIdx.x + s]);
        __syncthreads();
    }
    if (threadIdx.x == 0) atomicMax(&g_stat[1], __float_as_uint(sm[0]));
}

// ---------------- K8: SE MLP + output MLP ----------------
__global__ void k_out(const float* __restrict__ seW1, const float* __restrict__ seb1,
                      const float* __restrict__ seW2, const float* __restrict__ seb2,
                      const float* __restrict__ oW1, const float* __restrict__ ob1,
                      const float* __restrict__ oW2, const float* __restrict__ ob2,
                      const float* __restrict__ oW3, const float* __restrict__ ob3,
                      float* __restrict__ out) {
    int node = blockIdx.x;
    int t = threadIdx.x; // 64
    __shared__ float s1[32], scat[128], so1[64], so2[32];

    float degmax  = fmaxf(__uint_as_float(g_stat[0]), 1.f);
    float inflmax = fmaxf(__uint_as_float(g_stat[1]), 1e-12f);
    float nd   = g_deg[node]  / degmax;
    float infl = g_infl[node] / inflmax;

    if (t < 32) {
        float a = seb1[t] + nd * seW1[t] + infl * seW1[2 * 32 + t];
        s1[t] = fmaxf(a, 0.f);
    }
    scat[t] = g_h[(size_t)node * H + t];
    __syncthreads();

    {
        float a = seb2[t];
#pragma unroll
        for (int j = 0; j < 32; j++) a = fmaf(s1[j], seW2[j * 64 + t], a);
        scat[64 + t] = a;
    }
    __syncthreads();

    float a = ob1[t];
#pragma unroll 8
    for (int k = 0; k < 128; k++) a = fmaf(scat[k], oW1[k * 64 + t], a);
    so1[t] = fmaxf(a, 0.f);
    __syncthreads();

    if (t < 32) {
        float a2 = ob2[t];
#pragma unroll
        for (int k = 0; k < 64; k++) a2 = fmaf(so1[k], oW2[k * 32 + t], a2);
        so2[t] = fmaxf(a2, 0.f);
    }
    __syncthreads();

    if (t == 0) {
        float a3 = ob3[0];
#pragma unroll
        for (int k = 0; k < 32; k++) a3 = fmaf(so2[k], oW3[k], a3);
        out[node] = 1.f / (1.f + expf(-a3));
    }
}

// ---------------- launch ----------------
extern "C" void kernel_launch(void* const* d_in, const int* in_sizes, int n_in,
                              void* d_out, int out_size) {
    const float* x    = (const float*)d_in[0];
    const int*   ei   = (const int*)d_in[1];     // int32 on device (stub dtype set)
    const int*   src  = ei;
    const int*   dst  = ei + NE;
    const float* fa_W1  = (const float*)d_in[2];
    const float* fa_b1  = (const float*)d_in[3];
    const float* fa_W2  = (const float*)d_in[4];
    const float* fa_b2  = (const float*)d_in[5];
    const float* proj_W = (const float*)d_in[6];
    const float* proj_b = (const float*)d_in[7];
    const float* gat_W    = (const float*)d_in[8];
    const float* gat_asrc = (const float*)d_in[9];
    const float* gat_adst = (const float*)d_in[10];
    const float* gat_b    = (const float*)d_in[11];
    const float* bn_gamma = (const float*)d_in[12];
    const float* bn_beta  = (const float*)d_in[13];
    const float* bn_mean  = (const float*)d_in[14];
    const float* bn_var   = (const float*)d_in[15];
    const float* se_W1 = (const float*)d_in[16];
    const float* se_b1 = (const float*)d_in[17];
    const float* se_W2 = (const float*)d_in[18];
    const float* se_b2 = (const float*)d_in[19];
    const float* out_W1 = (const float*)d_in[20];
    const float* out_b1 = (const float*)d_in[21];
    const float* out_W2 = (const float*)d_in[22];
    const float* out_b2 = (const float*)d_in[23];
    const float* out_W3 = (const float*)d_in[24];
    const float* out_b3 = (const float*)d_in[25];
    float* out = (float*)d_out;

    k_feat<<<NN, 64>>>(x, fa_W1, fa_b1, fa_W2, fa_b2, proj_W, proj_b);

    for (int l = 0; l < 3; l++) {
        k_zproj<<<NN, 64>>>(gat_W + l * H * H, gat_asrc + l * H, gat_adst + l * H);
        k_init<<<(NN * H + 255) / 256, 256>>>();
        k_edge_max<<<(ETOT + 255) / 256, 256>>>(src, dst);
        k_edge_exp<<<(ETOT + 255) / 256, 256>>>(dst);
        {
            long long threads = (long long)ETOT * 32;
            int blocks = (int)((threads + 255) / 256);
            k_edge_agg<<<blocks, 256>>>(src, dst);
        }
        k_bn<<<(NN * H + 255) / 256, 256>>>(gat_b + l * H, bn_gamma + l * H,
                                            bn_beta + l * H, bn_mean + l * H,
                                            bn_var + l * H);
    }

    k_szero<<<(NN + 255) / 256, 256>>>();
    k_deg<<<(NE + 255) / 256, 256>>>(src);
    k_degmax<<<(NN + 255) / 256, 256>>>();
    k_infl<<<(NE + 255) / 256, 256>>>(src, dst);
    k_inflnorm<<<(NN + 255) / 256, 256>>>();

    k_out<<<NN, 64>>>(se_W1, se_b1, se_W2, se_b2,
                      out_W1, out_b1, out_W2, out_b2, out_W3, out_b3, out);
}

// round 3
// speedup vs baseline: 1.5090x; 1.5090x over previous
#include <cuda_runtime.h>
#include <math.h>

#define NN 100000
#define NE 1600000
#define D 128
#define H 64
#define SCAN_B 256
#define NBLK ((NN + SCAN_B - 1) / SCAN_B)   // 391

// ---------------- scratch (device globals; no allocation allowed) ----------
__device__ float g_h[NN * H];      // node features between stages
__device__ float g_z[NN * H];      // z = h @ W per layer
__device__ float g_zs[NN];
__device__ float g_zd[NN];
__device__ float g_deg[NN];
__device__ float g_infl[NN];
__device__ unsigned int g_stat[2]; // [0]=deg max bits, [1]=infl max bits
__device__ int g_cnt[NN];          // dst histogram
__device__ int g_offs[NN + 1];     // CSR offsets
__device__ int g_cur[NN];          // scatter cursors
__device__ int g_csr[NE];          // src indices grouped by dst
__device__ int g_bsum[512];        // scan block sums

// ---------------- K0: feature attention + projection --------------------
__global__ void k_feat(const float* __restrict__ x,
                       const float* __restrict__ W1, const float* __restrict__ b1,
                       const float* __restrict__ W2, const float* __restrict__ b2,
                       const float* __restrict__ Wp, const float* __restrict__ bp) {
    int node = blockIdx.x;
    int t = threadIdx.x;
    __shared__ float sx[D], st[H], sxf[D];
    sx[t]      = x[(size_t)node * D + t];
    sx[t + 64] = x[(size_t)node * D + t + 64];
    __syncthreads();

    float acc = b1[t];
#pragma unroll 8
    for (int k = 0; k < D; k++) acc = fmaf(sx[k], W1[k * H + t], acc);
    st[t] = fmaxf(acc, 0.f);
    __syncthreads();

#pragma unroll
    for (int r = 0; r < 2; r++) {
        int i = t + r * 64;
        float a = b2[i];
#pragma unroll 8
        for (int j = 0; j < H; j++) a = fmaf(st[j], W2[j * D + i], a);
        sxf[i] = sx[i] / (1.f + expf(-a));   // x * sigmoid(a)
    }
    __syncthreads();

    float hacc = bp[t];
#pragma unroll 8
    for (int k = 0; k < D; k++) hacc = fmaf(sxf[k], Wp[k * H + t], hacc);
    g_h[(size_t)node * H + t] = hacc;
}

// ---------------- CSR build ----------------
__global__ void k_zero() {
    int i = blockIdx.x * blockDim.x + threadIdx.x;
    if (i < NN) { g_cnt[i] = 0; g_deg[i] = 0.f; g_infl[i] = 0.f; }
    if (i < 2) g_stat[i] = 0u;
}
__global__ void k_hist(const int* __restrict__ src, const int* __restrict__ dst) {
    int i = blockIdx.x * blockDim.x + threadIdx.x;
    if (i >= NE) return;
    atomicAdd(&g_cnt[dst[i]], 1);
    atomicAdd(&g_deg[src[i]], 1.f);
}
__global__ void k_scan1() {
    __shared__ int sh[SCAN_B];
    int i = blockIdx.x * SCAN_B + threadIdx.x;
    int v = (i < NN) ? g_cnt[i] : 0;
    sh[threadIdx.x] = v;
    __syncthreads();
    for (int off = 1; off < SCAN_B; off <<= 1) {
        int add = (threadIdx.x >= off) ? sh[threadIdx.x - off] : 0;
        __syncthreads();
        sh[threadIdx.x] += add;
        __syncthreads();
    }
    if (i < NN) g_offs[i + 1] = sh[threadIdx.x];
    if (threadIdx.x == SCAN_B - 1) g_bsum[blockIdx.x] = sh[threadIdx.x];
}
__global__ void k_scan2() {
    __shared__ int sh[512];
    int t = threadIdx.x;
    sh[t] = (t < NBLK) ? g_bsum[t] : 0;
    __syncthreads();
    for (int off = 1; off < 512; off <<= 1) {
        int add = (t >= off) ? sh[t - off] : 0;
        __syncthreads();
        sh[t] += add;
        __syncthreads();
    }
    if (t < NBLK) g_bsum[t] = sh[t];
}
__global__ void k_scan3() {
    int i = blockIdx.x * SCAN_B + threadIdx.x;
    if (i >= NN) return;
    int blk = blockIdx.x;
    int pre = (blk > 0) ? g_bsum[blk - 1] : 0;
    int inc = g_offs[i + 1] + pre;
    g_offs[i + 1] = inc;
    g_cur[i] = inc - g_cnt[i];
    if (i == 0) g_offs[0] = 0;
}
__global__ void k_scatter(const int* __restrict__ src, const int* __restrict__ dst) {
    int i = blockIdx.x * blockDim.x + threadIdx.x;
    if (i >= NE) return;
    int d = dst[i];
    int pos = atomicAdd(&g_cur[d], 1);
    g_csr[pos] = src[i];
}

// ---------------- K1: z = h @ W, zs = z.a_src, zd = z.a_dst -------------
// 4 nodes per 256-thread block, W staged in shared
__global__ void k_zproj(const float* __restrict__ W,
                        const float* __restrict__ asrc,
                        const float* __restrict__ adst) {
    __shared__ float sW[H * H];
    __shared__ float sh[4][H];
    __shared__ float sa[H], sd[H];
    __shared__ float p1[4][2], p2[4][2];
    int tid = threadIdx.x;
    for (int i = tid; i < H * H; i += 256) sW[i] = W[i];
    if (tid < H) { sa[tid] = asrc[tid]; sd[tid] = adst[tid]; }
    int g = tid >> 6;
    int t = tid & 63;
    int node = blockIdx.x * 4 + g;
    sh[g][t] = g_h[(size_t)node * H + t];
    __syncthreads();

    float acc = 0.f;
#pragma unroll 16
    for (int k = 0; k < H; k++) acc = fmaf(sh[g][k], sW[k * H + t], acc);
    g_z[(size_t)node * H + t] = acc;

    float r1 = acc * sa[t];
    float r2 = acc * sd[t];
#pragma unroll
    for (int o = 16; o > 0; o >>= 1) {
        r1 += __shfl_down_sync(0xffffffff, r1, o);
        r2 += __shfl_down_sync(0xffffffff, r2, o);
    }
    if ((t & 31) == 0) { p1[g][t >> 5] = r1; p2[g][t >> 5] = r2; }
    __syncthreads();
    if (t == 0) {
        g_zs[node] = p1[g][0] + p1[g][1];
        g_zd[node] = p2[g][0] + p2[g][1];
    }
}

// ---------------- K2: fused GAT layer (warp per dst node) ----------------
// segment-max, softmax, weighted aggregation, bias+BN+ReLU — no atomics
__global__ void k_gat(const float* __restrict__ b, const float* __restrict__ gamma,
                      const float* __restrict__ beta, const float* __restrict__ mean,
                      const float* __restrict__ var) {
    int node = (blockIdx.x * blockDim.x + threadIdx.x) >> 5;
    int lane = threadIdx.x & 31;
    if (node >= NN) return;

    int beg = g_offs[node];
    int end = g_offs[node + 1];
    float zdn = g_zd[node];

    // self-loop logit
    float es = g_zs[node] + zdn;
    es = (es > 0.f) ? es : 0.2f * es;

    // pass 1: segment max
    float m = es;
    for (int j = beg + lane; j < end; j += 32) {
        float e = g_zs[g_csr[j]] + zdn;
        e = (e > 0.f) ? e : 0.2f * e;
        m = fmaxf(m, e);
    }
#pragma unroll
    for (int o = 16; o > 0; o >>= 1)
        m = fmaxf(m, __shfl_xor_sync(0xffffffff, m, o));

    // pass 2: accumulate exp-weighted sum + denom
    float exs = expf(es - m);
    float den = exs;
    const float* zself = g_z + (size_t)node * H;
    float acc0 = exs * zself[lane];
    float acc1 = exs * zself[lane + 32];

    for (int base = beg; base < end; base += 32) {
        int j = base + lane;
        float ex = 0.f;
        int s = 0;
        if (j < end) {
            s = g_csr[j];
            float e = g_zs[s] + zdn;
            e = (e > 0.f) ? e : 0.2f * e;
            ex = expf(e - m);
        }
        int nk = min(32, end - base);
        for (int k = 0; k < nk; k++) {
            float exk = __shfl_sync(0xffffffff, ex, k);
            int sk = __shfl_sync(0xffffffff, s, k);
            const float* zr = g_z + (size_t)sk * H;
            den += exk;
            acc0 = fmaf(exk, zr[lane], acc0);
            acc1 = fmaf(exk, zr[lane + 32], acc1);
        }
    }

    float inv = 1.f / den;
    float v0 = (acc0 * inv + b[lane] - mean[lane]) * rsqrtf(var[lane] + 1e-5f) * gamma[lane] + beta[lane];
    float v1 = (acc1 * inv + b[lane + 32] - mean[lane + 32]) * rsqrtf(var[lane + 32] + 1e-5f) * gamma[lane + 32] + beta[lane + 32];
    float* hr = g_h + (size_t)node * H;
    hr[lane]      = fmaxf(v0, 0.f);
    hr[lane + 32] = fmaxf(v1, 0.f);
}

// ---------------- structural ----------------
__global__ void k_degmax() {
    __shared__ float sm[256];
    int i = blockIdx.x * 256 + threadIdx.x;
    float v = (i < NN) ? g_deg[i] : 0.f;
    sm[threadIdx.x] = v;
    __syncthreads();
    for (int s = 128; s > 0; s >>= 1) {
        if (threadIdx.x < s) sm[threadIdx.x] = fmaxf(sm[threadIdx.x], sm[threadIdx.x + s]);
        __syncthreads();
    }
    if (threadIdx.x == 0) atomicMax(&g_stat[0], __float_as_uint(sm[0]));
}
__global__ void k_infl(const int* __restrict__ src, const int* __restrict__ dst) {
    int i = blockIdx.x * blockDim.x + threadIdx.x;
    if (i < NE) atomicAdd(&g_infl[src[i]], g_deg[dst[i]]);
}
__global__ void k_inflnorm() {
    __shared__ float sm[256];
    int i = blockIdx.x * 256 + threadIdx.x;
    float v = 0.f;
    if (i < NN) {
        float dg = g_deg[i];
        v = (dg > 0.f) ? g_infl[i] / fmaxf(dg, 1.f) : 0.f;
        g_infl[i] = v;
    }
    sm[threadIdx.x] = v;
    __syncthreads();
    for (int s = 128; s > 0; s >>= 1) {
        if (threadIdx.x < s) sm[threadIdx.x] = fmaxf(sm[threadIdx.x], sm[threadIdx.x + s]);
        __syncthreads();
    }
    if (threadIdx.x == 0) atomicMax(&g_stat[1], __float_as_uint(sm[0]));
}

// ---------------- K8: SE MLP + output MLP ----------------
__global__ void k_out(const float* __restrict__ seW1, const float* __restrict__ seb1,
                      const float* __restrict__ seW2, const float* __restrict__ seb2,
                      const float* __restrict__ oW1, const float* __restrict__ ob1,
                      const float* __restrict__ oW2, const float* __restrict__ ob2,
                      const float* __restrict__ oW3, const float* __restrict__ ob3,
                      float* __restrict__ out) {
    int node = blockIdx.x;
    int t = threadIdx.x; // 64
    __shared__ float s1[32], scat[128], so1[64], so2[32];

    float degmax  = fmaxf(__uint_as_float(g_stat[0]), 1.f);
    float inflmax = fmaxf(__uint_as_float(g_stat[1]), 1e-12f);
    float nd   = g_deg[node]  / degmax;
    float infl = g_infl[node] / inflmax;

    if (t < 32) {
        float a = seb1[t] + nd * seW1[t] + infl * seW1[2 * 32 + t];
        s1[t] = fmaxf(a, 0.f);
    }
    scat[t] = g_h[(size_t)node * H + t];
    __syncthreads();

    {
        float a = seb2[t];
#pragma unroll
        for (int j = 0; j < 32; j++) a = fmaf(s1[j], seW2[j * 64 + t], a);
        scat[64 + t] = a;
    }
    __syncthreads();

    float a = ob1[t];
#pragma unroll 8
    for (int k = 0; k < 128; k++) a = fmaf(scat[k], oW1[k * 64 + t], a);
    so1[t] = fmaxf(a, 0.f);
    __syncthreads();

    if (t < 32) {
        float a2 = ob2[t];
#pragma unroll
        for (int k = 0; k < 64; k++) a2 = fmaf(so1[k], oW2[k * 32 + t], a2);
        so2[t] = fmaxf(a2, 0.f);
    }
    __syncthreads();

    if (t == 0) {
        float a3 = ob3[0];
#pragma unroll
        for (int k = 0; k < 32; k++) a3 = fmaf(so2[k], oW3[k], a3);
        out[node] = 1.f / (1.f + expf(-a3));
    }
}

// ---------------- launch ----------------
extern "C" void kernel_launch(void* const* d_in, const int* in_sizes, int n_in,
                              void* d_out, int out_size) {
    const float* x    = (const float*)d_in[0];
    const int*   ei   = (const int*)d_in[1];     // int32 on device
    const int*   src  = ei;
    const int*   dst  = ei + NE;
    const float* fa_W1  = (const float*)d_in[2];
    const float* fa_b1  = (const float*)d_in[3];
    const float* fa_W2  = (const float*)d_in[4];
    const float* fa_b2  = (const float*)d_in[5];
    const float* proj_W = (const float*)d_in[6];
    const float* proj_b = (const float*)d_in[7];
    const float* gat_W    = (const float*)d_in[8];
    const float* gat_asrc = (const float*)d_in[9];
    const float* gat_adst = (const float*)d_in[10];
    const float* gat_b    = (const float*)d_in[11];
    const float* bn_gamma = (const float*)d_in[12];
    const float* bn_beta  = (const float*)d_in[13];
    const float* bn_mean  = (const float*)d_in[14];
    const float* bn_var   = (const float*)d_in[15];
    const float* se_W1 = (const float*)d_in[16];
    const float* se_b1 = (const float*)d_in[17];
    const float* se_W2 = (const float*)d_in[18];
    const float* se_b2 = (const float*)d_in[19];
    const float* out_W1 = (const float*)d_in[20];
    const float* out_b1 = (const float*)d_in[21];
    const float* out_W2 = (const float*)d_in[22];
    const float* out_b2 = (const float*)d_in[23];
    const float* out_W3 = (const float*)d_in[24];
    const float* out_b3 = (const float*)d_in[25];
    float* out = (float*)d_out;

    // CSR build (+ deg histogram fused) — overlaps nothing, runs once
    k_zero<<<(NN + 255) / 256, 256>>>();
    k_hist<<<(NE + 255) / 256, 256>>>(src, dst);
    k_scan1<<<NBLK, SCAN_B>>>();
    k_scan2<<<1, 512>>>();
    k_scan3<<<NBLK, SCAN_B>>>();
    k_scatter<<<(NE + 255) / 256, 256>>>(src, dst);

    k_feat<<<NN, 64>>>(x, fa_W1, fa_b1, fa_W2, fa_b2, proj_W, proj_b);

    for (int l = 0; l < 3; l++) {
        k_zproj<<<NN / 4, 256>>>(gat_W + l * H * H, gat_asrc + l * H, gat_adst + l * H);
        k_gat<<<(NN * 32 + 255) / 256, 256>>>(gat_b + l * H, bn_gamma + l * H,
                                              bn_beta + l * H, bn_mean + l * H,
                                              bn_var + l * H);
    }

    k_degmax<<<(NN + 255) / 256, 256>>>();
    k_infl<<<(NE + 255) / 256, 256>>>(src, dst);
    k_inflnorm<<<(NN + 255) / 256, 256>>>();

    k_out<<<NN, 64>>>(se_W1, se_b1, se_W2, se_b2,
                      out_W1, out_b1, out_W2, out_b2, out_W3, out_b3, out);
}

// round 4
// speedup vs baseline: 1.8878x; 1.2510x over previous
#include <cuda_runtime.h>
#include <math.h>

#define NN 100000
#define NE 1600000
#define D 128
#define H 64
#define SCAN_B 256
#define NBLK ((NN + SCAN_B - 1) / SCAN_B)   // 391

// ---------------- scratch (device globals) ----------------
__device__ float g_h[NN * H];
__device__ float g_z[NN * H];
__device__ float g_zs[NN];
__device__ float g_zd[NN];
__device__ float g_deg[NN];
__device__ float g_infl[NN];
__device__ unsigned int g_stat[2];
__device__ int g_cnt[NN];
__device__ int g_offs[NN + 1];
__device__ int g_cur[NN];
__device__ int g_csr[NE];
__device__ int g_bsum[512];

// ---------------- K0: feature attention + projection --------------------
// 128 threads, 8 nodes/block; 16 threads x float4 cols per node
__global__ void k_feat(const float* __restrict__ x,
                       const float* __restrict__ W1, const float* __restrict__ b1,
                       const float* __restrict__ W2, const float* __restrict__ b2,
                       const float* __restrict__ Wp, const float* __restrict__ bp) {
    __shared__ float sx[8][128];
    __shared__ float st[8][64];
    int tid = threadIdx.x;
    int nodeBase = blockIdx.x * 8;

    const float4* xg = (const float4*)(x + (size_t)nodeBase * 128);
    float4* sxv = (float4*)&sx[0][0];
    sxv[tid] = xg[tid];
    sxv[tid + 128] = xg[tid + 128];
    __syncthreads();

    int g = tid >> 4;
    int l = tid & 15;

    // stage 1: t1 = relu(x @ W1 + b1)  [K=128 -> O=64]
    float4 acc = *(const float4*)(b1 + 4 * l);
#pragma unroll 8
    for (int k = 0; k < 128; k++) {
        float xv = sx[g][k];
        float4 w = *(const float4*)(W1 + k * 64 + 4 * l);
        acc.x = fmaf(xv, w.x, acc.x);
        acc.y = fmaf(xv, w.y, acc.y);
        acc.z = fmaf(xv, w.z, acc.z);
        acc.w = fmaf(xv, w.w, acc.w);
    }
    {
        float4 r;
        r.x = fmaxf(acc.x, 0.f); r.y = fmaxf(acc.y, 0.f);
        r.z = fmaxf(acc.z, 0.f); r.w = fmaxf(acc.w, 0.f);
        *(float4*)(&st[g][4 * l]) = r;
    }
    __syncthreads();

    // stage 2: a = t1 @ W2 + b2  [K=64 -> O=128]; xf = x * sigmoid(a)
    float a[8];
    {
        float4 bb = *(const float4*)(b2 + 8 * l);
        float4 bc = *(const float4*)(b2 + 8 * l + 4);
        a[0] = bb.x; a[1] = bb.y; a[2] = bb.z; a[3] = bb.w;
        a[4] = bc.x; a[5] = bc.y; a[6] = bc.z; a[7] = bc.w;
    }
#pragma unroll 8
    for (int k = 0; k < 64; k++) {
        float tv = st[g][k];
        float4 wa = *(const float4*)(W2 + k * 128 + 8 * l);
        float4 wb = *(const float4*)(W2 + k * 128 + 8 * l + 4);
        a[0] = fmaf(tv, wa.x, a[0]); a[1] = fmaf(tv, wa.y, a[1]);
        a[2] = fmaf(tv, wa.z, a[2]); a[3] = fmaf(tv, wa.w, a[3]);
        a[4] = fmaf(tv, wb.x, a[4]); a[5] = fmaf(tv, wb.y, a[5]);
        a[6] = fmaf(tv, wb.z, a[6]); a[7] = fmaf(tv, wb.w, a[7]);
    }
#pragma unroll
    for (int j = 0; j < 8; j++) {
        int c = 8 * l + j;
        float s = 1.f / (1.f + __expf(-a[j]));
        sx[g][c] = sx[g][c] * s;
    }
    __syncthreads();

    // stage 3: h = xf @ Wp + bp  [K=128 -> O=64]
    float4 acc3 = *(const float4*)(bp + 4 * l);
#pragma unroll 8
    for (int k = 0; k < 128; k++) {
        float xv = sx[g][k];
        float4 w = *(const float4*)(Wp + k * 64 + 4 * l);
        acc3.x = fmaf(xv, w.x, acc3.x);
        acc3.y = fmaf(xv, w.y, acc3.y);
        acc3.z = fmaf(xv, w.z, acc3.z);
        acc3.w = fmaf(xv, w.w, acc3.w);
    }
    *(float4*)(g_h + (size_t)(nodeBase + g) * 64 + 4 * l) = acc3;
}

// ---------------- CSR build ----------------
__global__ void k_zero() {
    int i = blockIdx.x * blockDim.x + threadIdx.x;
    if (i < NN) { g_cnt[i] = 0; g_deg[i] = 0.f; g_infl[i] = 0.f; }
    if (i < 2) g_stat[i] = 0u;
}
__global__ void k_hist(const int* __restrict__ src, const int* __restrict__ dst) {
    int i = blockIdx.x * blockDim.x + threadIdx.x;
    if (i >= NE) return;
    atomicAdd(&g_cnt[dst[i]], 1);
    atomicAdd(&g_deg[src[i]], 1.f);
}
__global__ void k_scan1() {
    __shared__ int sh[SCAN_B];
    int i = blockIdx.x * SCAN_B + threadIdx.x;
    int v = (i < NN) ? g_cnt[i] : 0;
    sh[threadIdx.x] = v;
    __syncthreads();
    for (int off = 1; off < SCAN_B; off <<= 1) {
        int add = (threadIdx.x >= off) ? sh[threadIdx.x - off] : 0;
        __syncthreads();
        sh[threadIdx.x] += add;
        __syncthreads();
    }
    if (i < NN) g_offs[i + 1] = sh[threadIdx.x];
    if (threadIdx.x == SCAN_B - 1) g_bsum[blockIdx.x] = sh[threadIdx.x];
}
__global__ void k_scan2() {
    __shared__ int sh[512];
    int t = threadIdx.x;
    sh[t] = (t < NBLK) ? g_bsum[t] : 0;
    __syncthreads();
    for (int off = 1; off < 512; off <<= 1) {
        int add = (t >= off) ? sh[t - off] : 0;
        __syncthreads();
        sh[t] += add;
        __syncthreads();
    }
    if (t < NBLK) g_bsum[t] = sh[t];
}
__global__ void k_scan3() {
    int i = blockIdx.x * SCAN_B + threadIdx.x;
    if (i >= NN) return;
    int blk = blockIdx.x;
    int pre = (blk > 0) ? g_bsum[blk - 1] : 0;
    int inc = g_offs[i + 1] + pre;
    g_offs[i + 1] = inc;
    g_cur[i] = inc - g_cnt[i];
    if (i == 0) g_offs[0] = 0;
}
__global__ void k_scatter(const int* __restrict__ src, const int* __restrict__ dst) {
    int i = blockIdx.x * blockDim.x + threadIdx.x;
    if (i >= NE) return;
    int d = dst[i];
    int pos = atomicAdd(&g_cur[d], 1);
    g_csr[pos] = src[i];
}

// ---------------- K1: z = h @ W, zs, zd ----------------
// 128 threads, 8 nodes/block
__global__ void k_zproj(const float* __restrict__ W,
                        const float* __restrict__ asrc,
                        const float* __restrict__ adst) {
    __shared__ float sh[8][64];
    __shared__ float sa[64], sd[64];
    int tid = threadIdx.x;
    int nodeBase = blockIdx.x * 8;
    ((float4*)&sh[0][0])[tid] = ((const float4*)(g_h + (size_t)nodeBase * 64))[tid];
    if (tid < 64) { sa[tid] = asrc[tid]; sd[tid] = adst[tid]; }
    __syncthreads();

    int g = tid >> 4;
    int l = tid & 15;
    float4 acc = make_float4(0.f, 0.f, 0.f, 0.f);
#pragma unroll 8
    for (int k = 0; k < 64; k++) {
        float hv = sh[g][k];
        float4 w = *(const float4*)(W + k * 64 + 4 * l);
        acc.x = fmaf(hv, w.x, acc.x);
        acc.y = fmaf(hv, w.y, acc.y);
        acc.z = fmaf(hv, w.z, acc.z);
        acc.w = fmaf(hv, w.w, acc.w);
    }
    int node = nodeBase + g;
    *(float4*)(g_z + (size_t)node * 64 + 4 * l) = acc;

    int c = 4 * l;
    float p1 = acc.x * sa[c] + acc.y * sa[c + 1] + acc.z * sa[c + 2] + acc.w * sa[c + 3];
    float p2 = acc.x * sd[c] + acc.y * sd[c + 1] + acc.z * sd[c + 2] + acc.w * sd[c + 3];
#pragma unroll
    for (int o = 8; o > 0; o >>= 1) {
        p1 += __shfl_down_sync(0xffffffffu, p1, o, 16);
        p2 += __shfl_down_sync(0xffffffffu, p2, o, 16);
    }
    if (l == 0) { g_zs[node] = p1; g_zd[node] = p2; }
}

// ---------------- K2: fused GAT layer (warp per dst node) ----------------
__global__ void k_gat(const float* __restrict__ b, const float* __restrict__ gamma,
                      const float* __restrict__ beta, const float* __restrict__ mean,
                      const float* __restrict__ var) {
    int node = (blockIdx.x * blockDim.x + threadIdx.x) >> 5;
    int lane = threadIdx.x & 31;
    if (node >= NN) return;

    int beg = g_offs[node];
    int end = g_offs[node + 1];
    float zdn = g_zd[node];

    float es = g_zs[node] + zdn;
    es = (es > 0.f) ? es : 0.2f * es;

    float m = es;
    for (int j = beg + lane; j < end; j += 32) {
        float e = g_zs[g_csr[j]] + zdn;
        e = (e > 0.f) ? e : 0.2f * e;
        m = fmaxf(m, e);
    }
#pragma unroll
    for (int o = 16; o > 0; o >>= 1)
        m = fmaxf(m, __shfl_xor_sync(0xffffffffu, m, o));

    float exs = __expf(es - m);
    float den = exs;
    float2 zv = ((const float2*)(g_z + (size_t)node * 64))[lane];
    float2 acc = make_float2(exs * zv.x, exs * zv.y);

    for (int base = beg; base < end; base += 32) {
        int j = base + lane;
        float ex = 0.f;
        int s = 0;
        if (j < end) {
            s = g_csr[j];
            float e = g_zs[s] + zdn;
            e = (e > 0.f) ? e : 0.2f * e;
            ex = __expf(e - m);
        }
        int nk = min(32, end - base);
        for (int k = 0; k < nk; k++) {
            float exk = __shfl_sync(0xffffffffu, ex, k);
            int sk = __shfl_sync(0xffffffffu, s, k);
            float2 zr = ((const float2*)(g_z + (size_t)sk * 64))[lane];
            den += exk;
            acc.x = fmaf(exk, zr.x, acc.x);
            acc.y = fmaf(exk, zr.y, acc.y);
        }
    }

    float inv = 1.f / den;
    int j0 = 2 * lane, j1 = 2 * lane + 1;
    float v0 = (acc.x * inv + b[j0] - mean[j0]) * rsqrtf(var[j0] + 1e-5f) * gamma[j0] + beta[j0];
    float v1 = (acc.y * inv + b[j1] - mean[j1]) * rsqrtf(var[j1] + 1e-5f) * gamma[j1] + beta[j1];
    ((float2*)(g_h + (size_t)node * 64))[lane] = make_float2(fmaxf(v0, 0.f), fmaxf(v1, 0.f));
}

// ---------------- structural ----------------
__global__ void k_degmax() {
    __shared__ float sm[256];
    int i = blockIdx.x * 256 + threadIdx.x;
    float v = (i < NN) ? g_deg[i] : 0.f;
    sm[threadIdx.x] = v;
    __syncthreads();
    for (int s = 128; s > 0; s >>= 1) {
        if (threadIdx.x < s) sm[threadIdx.x] = fmaxf(sm[threadIdx.x], sm[threadIdx.x + s]);
        __syncthreads();
    }
    if (threadIdx.x == 0) atomicMax(&g_stat[0], __float_as_uint(sm[0]));
}
__global__ void k_infl(const int* __restrict__ src, const int* __restrict__ dst) {
    int i = blockIdx.x * blockDim.x + threadIdx.x;
    if (i < NE) atomicAdd(&g_infl[src[i]], g_deg[dst[i]]);
}
__global__ void k_inflnorm() {
    __shared__ float sm[256];
    int i = blockIdx.x * 256 + threadIdx.x;
    float v = 0.f;
    if (i < NN) {
        float dg = g_deg[i];
        v = (dg > 0.f) ? g_infl[i] / fmaxf(dg, 1.f) : 0.f;
        g_infl[i] = v;
    }
    sm[threadIdx.x] = v;
    __syncthreads();
    for (int s = 128; s > 0; s >>= 1) {
        if (threadIdx.x < s) sm[threadIdx.x] = fmaxf(sm[threadIdx.x], sm[threadIdx.x + s]);
        __syncthreads();
    }
    if (threadIdx.x == 0) atomicMax(&g_stat[1], __float_as_uint(sm[0]));
}

// ---------------- K8: SE MLP + output MLP (128 threads, 8 nodes) --------
__global__ void k_out(const float* __restrict__ seW1, const float* __restrict__ seb1,
                      const float* __restrict__ seW2, const float* __restrict__ seb2,
                      const float* __restrict__ oW1, const float* __restrict__ ob1,
                      const float* __restrict__ oW2, const float* __restrict__ ob2,
                      const float* __restrict__ oW3, const float* __restrict__ ob3,
                      float* __restrict__ out) {
    __shared__ float scat[8][128];
    __shared__ float ss1[8][32];
    __shared__ float so1[8][64];
    __shared__ float so2[8][32];
    int tid = threadIdx.x;
    int nodeBase = blockIdx.x * 8;
    int g = tid >> 4;
    int l = tid & 15;
    int node = nodeBase + g;

    ((float4*)&scat[g][0])[l] = ((const float4*)(g_h + (size_t)node * 64))[l];

    float degmax  = fmaxf(__uint_as_float(g_stat[0]), 1.f);
    float inflmax = fmaxf(__uint_as_float(g_stat[1]), 1e-12f);
    float nd   = g_deg[node]  / degmax;
    float infl = g_infl[node] / inflmax;

    // se stage1: 32 cols, 2 per thread
#pragma unroll
    for (int j = 0; j < 2; j++) {
        int c = 2 * l + j;
        float a = nd * seW1[c] + infl * seW1[64 + c] + seb1[c];
        ss1[g][c] = fmaxf(a, 0.f);
    }
    __syncthreads();

    // se stage2: K=32 -> O=64
    float4 a2 = *(const float4*)(seb2 + 4 * l);
#pragma unroll 8
    for (int k = 0; k < 32; k++) {
        float v = ss1[g][k];
        float4 w = *(const float4*)(seW2 + k * 64 + 4 * l);
        a2.x = fmaf(v, w.x, a2.x);
        a2.y = fmaf(v, w.y, a2.y);
        a2.z = fmaf(v, w.z, a2.z);
        a2.w = fmaf(v, w.w, a2.w);
    }
    *(float4*)(&scat[g][64 + 4 * l]) = a2;
    __syncthreads();

    // o1: K=128 -> O=64, relu
    float4 a = *(const float4*)(ob1 + 4 * l);
#pragma unroll 8
    for (int k = 0; k < 128; k++) {
        float v = scat[g][k];
        float4 w = *(const float4*)(oW1 + k * 64 + 4 * l);
        a.x = fmaf(v, w.x, a.x);
        a.y = fmaf(v, w.y, a.y);
        a.z = fmaf(v, w.z, a.z);
        a.w = fmaf(v, w.w, a.w);
    }
    {
        float4 r;
        r.x = fmaxf(a.x, 0.f); r.y = fmaxf(a.y, 0.f);
        r.z = fmaxf(a.z, 0.f); r.w = fmaxf(a.w, 0.f);
        *(float4*)(&so1[g][4 * l]) = r;
    }
    __syncthreads();

    // o2: K=64 -> O=32, relu
    float2 a22 = *(const float2*)(ob2 + 2 * l);
#pragma unroll 8
    for (int k = 0; k < 64; k++) {
        float v = so1[g][k];
        float2 w = *(const float2*)(oW2 + k * 32 + 2 * l);
        a22.x = fmaf(v, w.x, a22.x);
        a22.y = fmaf(v, w.y, a22.y);
    }
    so2[g][2 * l]     = fmaxf(a22.x, 0.f);
    so2[g][2 * l + 1] = fmaxf(a22.y, 0.f);
    __syncthreads();

    // o3: K=32 -> 1, sigmoid
    float p = so2[g][l] * oW3[l] + so2[g][l + 16] * oW3[l + 16];
#pragma unroll
    for (int o = 8; o > 0; o >>= 1)
        p += __shfl_down_sync(0xffffffffu, p, o, 16);
    if (l == 0)
        out[node] = 1.f / (1.f + __expf(-(p + ob3[0])));
}

// ---------------- launch ----------------
extern "C" void kernel_launch(void* const* d_in, const int* in_sizes, int n_in,
                              void* d_out, int out_size) {
    const float* x    = (const float*)d_in[0];
    const int*   ei   = (const int*)d_in[1];
    const int*   src  = ei;
    const int*   dst  = ei + NE;
    const float* fa_W1  = (const float*)d_in[2];
    const float* fa_b1  = (const float*)d_in[3];
    const float* fa_W2  = (const float*)d_in[4];
    const float* fa_b2  = (const float*)d_in[5];
    const float* proj_W = (const float*)d_in[6];
    const float* proj_b = (const float*)d_in[7];
    const float* gat_W    = (const float*)d_in[8];
    const float* gat_asrc = (const float*)d_in[9];
    const float* gat_adst = (const float*)d_in[10];
    const float* gat_b    = (const float*)d_in[11];
    const float* bn_gamma = (const float*)d_in[12];
    const float* bn_beta  = (const float*)d_in[13];
    const float* bn_mean  = (const float*)d_in[14];
    const float* bn_var   = (const float*)d_in[15];
    const float* se_W1 = (const float*)d_in[16];
    const float* se_b1 = (const float*)d_in[17];
    const float* se_W2 = (const float*)d_in[18];
    const float* se_b2 = (const float*)d_in[19];
    const float* out_W1 = (const float*)d_in[20];
    const float* out_b1 = (const float*)d_in[21];
    const float* out_W2 = (const float*)d_in[22];
    const float* out_b2 = (const float*)d_in[23];
    const float* out_W3 = (const float*)d_in[24];
    const float* out_b3 = (const float*)d_in[25];
    float* out = (float*)d_out;

    k_zero<<<(NN + 255) / 256, 256>>>();
    k_hist<<<(NE + 255) / 256, 256>>>(src, dst);
    k_scan1<<<NBLK, SCAN_B>>>();
    k_scan2<<<1, 512>>>();
    k_scan3<<<NBLK, SCAN_B>>>();
    k_scatter<<<(NE + 255) / 256, 256>>>(src, dst);

    k_feat<<<NN / 8, 128>>>(x, fa_W1, fa_b1, fa_W2, fa_b2, proj_W, proj_b);

    for (int l = 0; l < 3; l++) {
        k_zproj<<<NN / 8, 128>>>(gat_W + l * H * H, gat_asrc + l * H, gat_adst + l * H);
        k_gat<<<(NN * 32 + 255) / 256, 256>>>(gat_b + l * H, bn_gamma + l * H,
                                              bn_beta + l * H, bn_mean + l * H,
                                              bn_var + l * H);
    }

    k_degmax<<<(NN + 255) / 256, 256>>>();
    k_infl<<<(NE + 255) / 256, 256>>>(src, dst);
    k_inflnorm<<<(NN + 255) / 256, 256>>>();

    k_out<<<NN / 8, 128>>>(se_W1, se_b1, se_W2, se_b2,
                           out_W1, out_b1, out_W2, out_b2, out_W3, out_b3, out);
}

// round 5
// speedup vs baseline: 2.5388x; 1.3449x over previous
#include <cuda_runtime.h>
#include <math.h>

#define NN 100000
#define NE 1600000
#define D 128
#define H 64
#define SCAN_B 256
#define NBLK ((NN + SCAN_B - 1) / SCAN_B)   // 391

// ---------------- scratch (device globals) ----------------
__device__ float g_h[NN * H];
__device__ float g_z[NN * H];
__device__ float g_zs[NN];
__device__ float g_zd[NN];
__device__ float g_deg[NN];
__device__ float g_infl[NN];
__device__ unsigned int g_stat[2];
__device__ int g_cnt[NN];
__device__ int g_offs[NN + 1];
__device__ int g_cur[NN];
__device__ int g_csr[NE];
__device__ int g_bsum[512];

// ---------------- packed fp32x2 helpers ----------------
__device__ __forceinline__ unsigned long long ffma2(unsigned long long a,
                                                    unsigned long long b,
                                                    unsigned long long c) {
    unsigned long long d;
    asm("fma.rn.f32x2 %0, %1, %2, %3;" : "=l"(d) : "l"(a), "l"(b), "l"(c));
    return d;
}
__device__ __forceinline__ unsigned long long pk2(float x) {
    unsigned long long r;
    asm("mov.b64 %0, {%1, %1};" : "=l"(r) : "f"(x));
    return r;
}
__device__ __forceinline__ float2 up2(unsigned long long v) {
    float2 f;
    asm("mov.b64 {%0, %1}, %2;" : "=f"(f.x), "=f"(f.y) : "l"(v));
    return f;
}

// ---------------- K0: feature attention + projection --------------------
// 128 threads, 16 nodes/block, 2 nodes/thread, f32x2 FMA
__global__ void __launch_bounds__(128) k_feat(
        const float* __restrict__ x,
        const float* __restrict__ W1, const float* __restrict__ b1,
        const float* __restrict__ W2, const float* __restrict__ b2,
        const float* __restrict__ Wp, const float* __restrict__ bp) {
    __shared__ float sx[16 * 128];
    __shared__ float st[16 * 64];
    int tid = threadIdx.x;
    int nodeBase = blockIdx.x * 16;

    const float4* xg = (const float4*)(x + (size_t)nodeBase * 128);
    float4* sxv = (float4*)sx;
#pragma unroll
    for (int i = 0; i < 4; i++) sxv[tid + i * 128] = xg[tid + i * 128];
    __syncthreads();

    int g = tid >> 4;
    int l = tid & 15;
    const float* x0 = sx + g * 128;
    const float* x1 = sx + (g + 8) * 128;

    // stage 1: t = relu(x @ W1 + b1)   [K=128 -> O=64]
    {
        ulonglong2 bb = *(const ulonglong2*)(b1 + 4 * l);
        unsigned long long a0x = bb.x, a0y = bb.y, a1x = bb.x, a1y = bb.y;
#pragma unroll 4
        for (int k = 0; k < 128; k++) {
            ulonglong2 w = *(const ulonglong2*)(W1 + k * 64 + 4 * l);
            unsigned long long v0 = pk2(x0[k]), v1 = pk2(x1[k]);
            a0x = ffma2(v0, w.x, a0x); a0y = ffma2(v0, w.y, a0y);
            a1x = ffma2(v1, w.x, a1x); a1y = ffma2(v1, w.y, a1y);
        }
        float2 p, q;
        float* s0 = st + g * 64 + 4 * l;
        float* s1 = st + (g + 8) * 64 + 4 * l;
        p = up2(a0x); q = up2(a0y);
        s0[0] = fmaxf(p.x, 0.f); s0[1] = fmaxf(p.y, 0.f);
        s0[2] = fmaxf(q.x, 0.f); s0[3] = fmaxf(q.y, 0.f);
        p = up2(a1x); q = up2(a1y);
        s1[0] = fmaxf(p.x, 0.f); s1[1] = fmaxf(p.y, 0.f);
        s1[2] = fmaxf(q.x, 0.f); s1[3] = fmaxf(q.y, 0.f);
    }
    __syncthreads();

    // stage 2: a = t @ W2 + b2  [K=64 -> O=128]; x *= sigmoid(a)
    {
        ulonglong2 c0 = *(const ulonglong2*)(b2 + 8 * l);
        ulonglong2 c1 = *(const ulonglong2*)(b2 + 8 * l + 4);
        unsigned long long a00 = c0.x, a01 = c0.y, a02 = c1.x, a03 = c1.y;
        unsigned long long a10 = c0.x, a11 = c0.y, a12 = c1.x, a13 = c1.y;
        const float* t0 = st + g * 64;
        const float* t1 = st + (g + 8) * 64;
#pragma unroll 4
        for (int k = 0; k < 64; k++) {
            ulonglong2 wa = *(const ulonglong2*)(W2 + k * 128 + 8 * l);
            ulonglong2 wb = *(const ulonglong2*)(W2 + k * 128 + 8 * l + 4);
            unsigned long long v0 = pk2(t0[k]), v1 = pk2(t1[k]);
            a00 = ffma2(v0, wa.x, a00); a01 = ffma2(v0, wa.y, a01);
            a02 = ffma2(v0, wb.x, a02); a03 = ffma2(v0, wb.y, a03);
            a10 = ffma2(v1, wa.x, a10); a11 = ffma2(v1, wa.y, a11);
            a12 = ffma2(v1, wb.x, a12); a13 = ffma2(v1, wb.y, a13);
        }
        float av[8];
        float2 p;
        float* r0 = sx + g * 128 + 8 * l;
        p = up2(a00); av[0] = p.x; av[1] = p.y;
        p = up2(a01); av[2] = p.x; av[3] = p.y;
        p = up2(a02); av[4] = p.x; av[5] = p.y;
        p = up2(a03); av[6] = p.x; av[7] = p.y;
#pragma unroll
        for (int j = 0; j < 8; j++) r0[j] *= 1.f / (1.f + __expf(-av[j]));
        float* r1 = sx + (g + 8) * 128 + 8 * l;
        p = up2(a10); av[0] = p.x; av[1] = p.y;
        p = up2(a11); av[2] = p.x; av[3] = p.y;
        p = up2(a12); av[4] = p.x; av[5] = p.y;
        p = up2(a13); av[6] = p.x; av[7] = p.y;
#pragma unroll
        for (int j = 0; j < 8; j++) r1[j] *= 1.f / (1.f + __expf(-av[j]));
    }
    __syncthreads();

    // stage 3: h = xf @ Wp + bp  [K=128 -> O=64]
    {
        ulonglong2 bb = *(const ulonglong2*)(bp + 4 * l);
        unsigned long long a0x = bb.x, a0y = bb.y, a1x = bb.x, a1y = bb.y;
#pragma unroll 4
        for (int k = 0; k < 128; k++) {
            ulonglong2 w = *(const ulonglong2*)(Wp + k * 64 + 4 * l);
            unsigned long long v0 = pk2(x0[k]), v1 = pk2(x1[k]);
            a0x = ffma2(v0, w.x, a0x); a0y = ffma2(v0, w.y, a0y);
            a1x = ffma2(v1, w.x, a1x); a1y = ffma2(v1, w.y, a1y);
        }
        ulonglong2* h0 = (ulonglong2*)(g_h + (size_t)(nodeBase + g) * 64 + 4 * l);
        ulonglong2* h1 = (ulonglong2*)(g_h + (size_t)(nodeBase + g + 8) * 64 + 4 * l);
        h0->x = a0x; h0->y = a0y;
        h1->x = a1x; h1->y = a1y;
    }
}

// ---------------- CSR build ----------------
__global__ void k_zero() {
    int i = blockIdx.x * blockDim.x + threadIdx.x;
    if (i < NN) { g_cnt[i] = 0; g_deg[i] = 0.f; g_infl[i] = 0.f; }
    if (i < 2) g_stat[i] = 0u;
}
__global__ void k_hist(const int* __restrict__ src, const int* __restrict__ dst) {
    int i = blockIdx.x * blockDim.x + threadIdx.x;
    if (i >= NE) return;
    atomicAdd(&g_cnt[dst[i]], 1);
    atomicAdd(&g_deg[src[i]], 1.f);
}
__global__ void k_scan1() {
    __shared__ int sh[SCAN_B];
    int i = blockIdx.x * SCAN_B + threadIdx.x;
    int v = (i < NN) ? g_cnt[i] : 0;
    sh[threadIdx.x] = v;
    __syncthreads();
    for (int off = 1; off < SCAN_B; off <<= 1) {
        int add = (threadIdx.x >= off) ? sh[threadIdx.x - off] : 0;
        __syncthreads();
        sh[threadIdx.x] += add;
        __syncthreads();
    }
    if (i < NN) g_offs[i + 1] = sh[threadIdx.x];
    if (threadIdx.x == SCAN_B - 1) g_bsum[blockIdx.x] = sh[threadIdx.x];
}
__global__ void k_scan2() {
    __shared__ int sh[512];
    int t = threadIdx.x;
    sh[t] = (t < NBLK) ? g_bsum[t] : 0;
    __syncthreads();
    for (int off = 1; off < 512; off <<= 1) {
        int add = (t >= off) ? sh[t - off] : 0;
        __syncthreads();
        sh[t] += add;
        __syncthreads();
    }
    if (t < NBLK) g_bsum[t] = sh[t];
}
__global__ void k_scan3() {
    int i = blockIdx.x * SCAN_B + threadIdx.x;
    if (i >= NN) return;
    int blk = blockIdx.x;
    int pre = (blk > 0) ? g_bsum[blk - 1] : 0;
    int inc = g_offs[i + 1] + pre;
    g_offs[i + 1] = inc;
    g_cur[i] = inc - g_cnt[i];
    if (i == 0) g_offs[0] = 0;
}
__global__ void k_scatter(const int* __restrict__ src, const int* __restrict__ dst) {
    int i = blockIdx.x * blockDim.x + threadIdx.x;
    if (i >= NE) return;
    int d = dst[i];
    int pos = atomicAdd(&g_cur[d], 1);
    g_csr[pos] = src[i];
}

// ---------------- K1: z = h @ W, zs, zd ----------------
// 128 threads, 16 nodes/block, 2 nodes/thread
__global__ void __launch_bounds__(128) k_zproj(
        const float* __restrict__ W,
        const float* __restrict__ asrc,
        const float* __restrict__ adst) {
    __shared__ float sh[16 * 64];
    __shared__ float sa[64], sd[64];
    int tid = threadIdx.x;
    int nodeBase = blockIdx.x * 16;
    ((float4*)sh)[tid]       = ((const float4*)(g_h + (size_t)nodeBase * 64))[tid];
    ((float4*)sh)[tid + 128] = ((const float4*)(g_h + (size_t)nodeBase * 64))[tid + 128];
    if (tid < 64) { sa[tid] = asrc[tid]; sd[tid] = adst[tid]; }
    __syncthreads();

    int g = tid >> 4;
    int l = tid & 15;
    const float* h0 = sh + g * 64;
    const float* h1 = sh + (g + 8) * 64;
    unsigned long long a0x = 0, a0y = 0, a1x = 0, a1y = 0;
#pragma unroll 4
    for (int k = 0; k < 64; k++) {
        ulonglong2 w = *(const ulonglong2*)(W + k * 64 + 4 * l);
        unsigned long long v0 = pk2(h0[k]), v1 = pk2(h1[k]);
        a0x = ffma2(v0, w.x, a0x); a0y = ffma2(v0, w.y, a0y);
        a1x = ffma2(v1, w.x, a1x); a1y = ffma2(v1, w.y, a1y);
    }
    int n0 = nodeBase + g;
    int n1 = nodeBase + g + 8;
    {
        ulonglong2* z0 = (ulonglong2*)(g_z + (size_t)n0 * 64 + 4 * l);
        ulonglong2* z1 = (ulonglong2*)(g_z + (size_t)n1 * 64 + 4 * l);
        z0->x = a0x; z0->y = a0y;
        z1->x = a1x; z1->y = a1y;
    }
    int c = 4 * l;
    float2 p0 = up2(a0x), q0 = up2(a0y), p1 = up2(a1x), q1 = up2(a1y);
    float s0 = p0.x * sa[c] + p0.y * sa[c + 1] + q0.x * sa[c + 2] + q0.y * sa[c + 3];
    float d0 = p0.x * sd[c] + p0.y * sd[c + 1] + q0.x * sd[c + 2] + q0.y * sd[c + 3];
    float s1 = p1.x * sa[c] + p1.y * sa[c + 1] + q1.x * sa[c + 2] + q1.y * sa[c + 3];
    float d1 = p1.x * sd[c] + p1.y * sd[c + 1] + q1.x * sd[c + 2] + q1.y * sd[c + 3];
#pragma unroll
    for (int o = 8; o > 0; o >>= 1) {
        s0 += __shfl_down_sync(0xffffffffu, s0, o, 16);
        d0 += __shfl_down_sync(0xffffffffu, d0, o, 16);
        s1 += __shfl_down_sync(0xffffffffu, s1, o, 16);
        d1 += __shfl_down_sync(0xffffffffu, d1, o, 16);
    }
    if (l == 0) {
        g_zs[n0] = s0; g_zd[n0] = d0;
        g_zs[n1] = s1; g_zd[n1] = d1;
    }
}

// ---------------- K2: fused GAT layer (warp per dst node) ----------------
__global__ void k_gat(const float* __restrict__ b, const float* __restrict__ gamma,
                      const float* __restrict__ beta, const float* __restrict__ mean,
                      const float* __restrict__ var) {
    int node = (blockIdx.x * blockDim.x + threadIdx.x) >> 5;
    int lane = threadIdx.x & 31;
    if (node >= NN) return;

    int beg = g_offs[node];
    int end = g_offs[node + 1];
    float zdn = g_zd[node];

    float es = g_zs[node] + zdn;
    es = (es > 0.f) ? es : 0.2f * es;

    float m = es;
    for (int j = beg + lane; j < end; j += 32) {
        float e = g_zs[g_csr[j]] + zdn;
        e = (e > 0.f) ? e : 0.2f * e;
        m = fmaxf(m, e);
    }
#pragma unroll
    for (int o = 16; o > 0; o >>= 1)
        m = fmaxf(m, __shfl_xor_sync(0xffffffffu, m, o));

    float exs = __expf(es - m);
    float den = exs;
    float2 zv = ((const float2*)(g_z + (size_t)node * 64))[lane];
    float2 acc = make_float2(exs * zv.x, exs * zv.y);

    for (int base = beg; base < end; base += 32) {
        int j = base + lane;
        float ex = 0.f;
        int s = 0;
        if (j < end) {
            s = g_csr[j];
            float e = g_zs[s] + zdn;
            e = (e > 0.f) ? e : 0.2f * e;
            ex = __expf(e - m);
        }
        int nk = min(32, end - base);
        for (int k = 0; k < nk; k++) {
            float exk = __shfl_sync(0xffffffffu, ex, k);
            int sk = __shfl_sync(0xffffffffu, s, k);
            float2 zr = ((const float2*)(g_z + (size_t)sk * 64))[lane];
            den += exk;
            acc.x = fmaf(exk, zr.x, acc.x);
            acc.y = fmaf(exk, zr.y, acc.y);
        }
    }

    float inv = 1.f / den;
    int j0 = 2 * lane, j1 = 2 * lane + 1;
    float v0 = (acc.x * inv + b[j0] - mean[j0]) * rsqrtf(var[j0] + 1e-5f) * gamma[j0] + beta[j0];
    float v1 = (acc.y * inv + b[j1] - mean[j1]) * rsqrtf(var[j1] + 1e-5f) * gamma[j1] + beta[j1];
    ((float2*)(g_h + (size_t)node * 64))[lane] = make_float2(fmaxf(v0, 0.f), fmaxf(v1, 0.f));
}

// ---------------- structural ----------------
__global__ void k_degmax() {
    __shared__ float sm[256];
    int i = blockIdx.x * 256 + threadIdx.x;
    float v = (i < NN) ? g_deg[i] : 0.f;
    sm[threadIdx.x] = v;
    __syncthreads();
    for (int s = 128; s > 0; s >>= 1) {
        if (threadIdx.x < s) sm[threadIdx.x] = fmaxf(sm[threadIdx.x], sm[threadIdx.x + s]);
        __syncthreads();
    }
    if (threadIdx.x == 0) atomicMax(&g_stat[0], __float_as_uint(sm[0]));
}
__global__ void k_infl(const int* __restrict__ src, const int* __restrict__ dst) {
    int i = blockIdx.x * blockDim.x + threadIdx.x;
    if (i < NE) atomicAdd(&g_infl[src[i]], g_deg[dst[i]]);
}
__global__ void k_inflnorm() {
    __shared__ float sm[256];
    int i = blockIdx.x * 256 + threadIdx.x;
    float v = 0.f;
    if (i < NN) {
        float dg = g_deg[i];
        v = (dg > 0.f) ? g_infl[i] / fmaxf(dg, 1.f) : 0.f;
        g_infl[i] = v;
    }
    sm[threadIdx.x] = v;
    __syncthreads();
    for (int s = 128; s > 0; s >>= 1) {
        if (threadIdx.x < s) sm[threadIdx.x] = fmaxf(sm[threadIdx.x], sm[threadIdx.x + s]);
        __syncthreads();
    }
    if (threadIdx.x == 0) atomicMax(&g_stat[1], __float_as_uint(sm[0]));
}

// ---------------- K8: SE MLP + output MLP (16 nodes/block) --------------
__global__ void __launch_bounds__(128) k_out(
        const float* __restrict__ seW1, const float* __restrict__ seb1,
        const float* __restrict__ seW2, const float* __restrict__ seb2,
        const float* __restrict__ oW1, const float* __restrict__ ob1,
        const float* __restrict__ oW2, const float* __restrict__ ob2,
        const float* __restrict__ oW3, const float* __restrict__ ob3,
        float* __restrict__ out) {
    __shared__ float scat[16 * 128];
    __shared__ float ss1[16 * 32];
    __shared__ float so1[16 * 64];
    __shared__ float so2[16 * 32];
    int tid = threadIdx.x;
    int nodeBase = blockIdx.x * 16;
    int g = tid >> 4;
    int l = tid & 15;
    int n0 = nodeBase + g;
    int n1 = nodeBase + g + 8;

    // load h rows (first 64 cols of scat)
#pragma unroll
    for (int i = 0; i < 2; i++) {
        int idx = tid + i * 128;       // 0..255
        int r = idx >> 4, c4 = idx & 15;
        ((float4*)&scat[r * 128])[c4] =
            ((const float4*)(g_h + (size_t)(nodeBase + r) * 64))[c4];
    }

    float degmax  = fmaxf(__uint_as_float(g_stat[0]), 1.f);
    float inflmax = fmaxf(__uint_as_float(g_stat[1]), 1e-12f);

    // se stage1: O=32, 2 cols per thread per node
    {
        float nd0 = g_deg[n0] / degmax, in0 = g_infl[n0] / inflmax;
        float nd1 = g_deg[n1] / degmax, in1 = g_infl[n1] / inflmax;
#pragma unroll
        for (int j = 0; j < 2; j++) {
            int c = 2 * l + j;
            float w0 = seW1[c], w2 = seW1[64 + c], bb = seb1[c];
            ss1[g * 32 + c]       = fmaxf(nd0 * w0 + in0 * w2 + bb, 0.f);
            ss1[(g + 8) * 32 + c] = fmaxf(nd1 * w0 + in1 * w2 + bb, 0.f);
        }
    }
    __syncthreads();

    // se stage2: K=32 -> O=64, into scat cols 64..127
    {
        ulonglong2 bb = *(const ulonglong2*)(seb2 + 4 * l);
        unsigned long long a0x = bb.x, a0y = bb.y, a1x = bb.x, a1y = bb.y;
        const float* t0 = ss1 + g * 32;
        const float* t1 = ss1 + (g + 8) * 32;
#pragma unroll 4
        for (int k = 0; k < 32; k++) {
            ulonglong2 w = *(const ulonglong2*)(seW2 + k * 64 + 4 * l);
            unsigned long long v0 = pk2(t0[k]), v1 = pk2(t1[k]);
            a0x = ffma2(v0, w.x, a0x); a0y = ffma2(v0, w.y, a0y);
            a1x = ffma2(v1, w.x, a1x); a1y = ffma2(v1, w.y, a1y);
        }
        ulonglong2* p0 = (ulonglong2*)&scat[g * 128 + 64 + 4 * l];
        ulonglong2* p1 = (ulonglong2*)&scat[(g + 8) * 128 + 64 + 4 * l];
        p0->x = a0x; p0->y = a0y;
        p1->x = a1x; p1->y = a1y;
    }
    __syncthreads();

    // o1: K=128 -> O=64, relu
    {
        ulonglong2 bb = *(const ulonglong2*)(ob1 + 4 * l);
        unsigned long long a0x = bb.x, a0y = bb.y, a1x = bb.x, a1y = bb.y;
        const float* c0 = scat + g * 128;
        const float* c1 = scat + (g + 8) * 128;
#pragma unroll 4
        for (int k = 0; k < 128; k++) {
            ulonglong2 w = *(const ulonglong2*)(oW1 + k * 64 + 4 * l);
            unsigned long long v0 = pk2(c0[k]), v1 = pk2(c1[k]);
            a0x = ffma2(v0, w.x, a0x); a0y = ffma2(v0, w.y, a0y);
            a1x = ffma2(v1, w.x, a1x); a1y = ffma2(v1, w.y, a1y);
        }
        float2 p, q;
        float* s0 = so1 + g * 64 + 4 * l;
        float* s1 = so1 + (g + 8) * 64 + 4 * l;
        p = up2(a0x); q = up2(a0y);
        s0[0] = fmaxf(p.x, 0.f); s0[1] = fmaxf(p.y, 0.f);
        s0[2] = fmaxf(q.x, 0.f); s0[3] = fmaxf(q.y, 0.f);
        p = up2(a1x); q = up2(a1y);
        s1[0] = fmaxf(p.x, 0.f); s1[1] = fmaxf(p.y, 0.f);
        s1[2] = fmaxf(q.x, 0.f); s1[3] = fmaxf(q.y, 0.f);
    }
    __syncthreads();

    // o2: K=64 -> O=32, relu (2 cols per thread per node)
    {
        unsigned long long bb = *(const unsigned long long*)(ob2 + 2 * l);
        unsigned long long a0 = bb, a1 = bb;
        const float* t0 = so1 + g * 64;
        const float* t1 = so1 + (g + 8) * 64;
#pragma unroll 4
        for (int k = 0; k < 64; k++) {
            unsigned long long w = *(const unsigned long long*)(oW2 + k * 32 + 2 * l);
            a0 = ffma2(pk2(t0[k]), w, a0);
            a1 = ffma2(pk2(t1[k]), w, a1);
        }
        float2 p = up2(a0);
        so2[g * 32 + 2 * l]     = fmaxf(p.x, 0.f);
        so2[g * 32 + 2 * l + 1] = fmaxf(p.y, 0.f);
        p = up2(a1);
        so2[(g + 8) * 32 + 2 * l]     = fmaxf(p.x, 0.f);
        so2[(g + 8) * 32 + 2 * l + 1] = fmaxf(p.y, 0.f);
    }
    __syncthreads();

    // o3: K=32 -> 1, sigmoid
    {
        float w0 = oW3[l], w1 = oW3[l + 16];
        float p0 = so2[g * 32 + l] * w0 + so2[g * 32 + l + 16] * w1;
        float p1 = so2[(g + 8) * 32 + l] * w0 + so2[(g + 8) * 32 + l + 16] * w1;
#pragma unroll
        for (int o = 8; o > 0; o >>= 1) {
            p0 += __shfl_down_sync(0xffffffffu, p0, o, 16);
            p1 += __shfl_down_sync(0xffffffffu, p1, o, 16);
        }
        if (l == 0) {
            float bb = ob3[0];
            out[n0] = 1.f / (1.f + __expf(-(p0 + bb)));
            out[n1] = 1.f / (1.f + __expf(-(p1 + bb)));
        }
    }
}

// ---------------- launch ----------------
extern "C" void kernel_launch(void* const* d_in, const int* in_sizes, int n_in,
                              void* d_out, int out_size) {
    const float* x    = (const float*)d_in[0];
    const int*   ei   = (const int*)d_in[1];
    const int*   src  = ei;
    const int*   dst  = ei + NE;
    const float* fa_W1  = (const float*)d_in[2];
    const float* fa_b1  = (const float*)d_in[3];
    const float* fa_W2  = (const float*)d_in[4];
    const float* fa_b2  = (const float*)d_in[5];
    const float* proj_W = (const float*)d_in[6];
    const float* proj_b = (const float*)d_in[7];
    const float* gat_W    = (const float*)d_in[8];
    const float* gat_asrc = (const float*)d_in[9];
    const float* gat_adst = (const float*)d_in[10];
    const float* gat_b    = (const float*)d_in[11];
    const float* bn_gamma = (const float*)d_in[12];
    const float* bn_beta  = (const float*)d_in[13];
    const float* bn_mean  = (const float*)d_in[14];
    const float* bn_var   = (const float*)d_in[15];
    const float* se_W1 = (const float*)d_in[16];
    const float* se_b1 = (const float*)d_in[17];
    const float* se_W2 = (const float*)d_in[18];
    const float* se_b2 = (const float*)d_in[19];
    const float* out_W1 = (const float*)d_in[20];
    const float* out_b1 = (const float*)d_in[21];
    const float* out_W2 = (const float*)d_in[22];
    const float* out_b2 = (const float*)d_in[23];
    const float* out_W3 = (const float*)d_in[24];
    const float* out_b3 = (const float*)d_in[25];
    float* out = (float*)d_out;

    k_zero<<<(NN + 255) / 256, 256>>>();
    k_hist<<<(NE + 255) / 256, 256>>>(src, dst);
    k_scan1<<<NBLK, SCAN_B>>>();
    k_scan2<<<1, 512>>>();
    k_scan3<<<NBLK, SCAN_B>>>();
    k_scatter<<<(NE + 255) / 256, 256>>>(src, dst);

    k_feat<<<NN / 16, 128>>>(x, fa_W1, fa_b1, fa_W2, fa_b2, proj_W, proj_b);

    for (int l = 0; l < 3; l++) {
        k_zproj<<<NN / 16, 128>>>(gat_W + l * H * H, gat_asrc + l * H, gat_adst + l * H);
        k_gat<<<(NN * 32 + 255) / 256, 256>>>(gat_b + l * H, bn_gamma + l * H,
                                              bn_beta + l * H, bn_mean + l * H,
                                              bn_var + l * H);
    }

    k_degmax<<<(NN + 255) / 256, 256>>>();
    k_infl<<<(NE + 255) / 256, 256>>>(src, dst);
    k_inflnorm<<<(NN + 255) / 256, 256>>>();

    k_out<<<NN / 16, 128>>>(se_W1, se_b1, se_W2, se_b2,
                            out_W1, out_b1, out_W2, out_b2, out_W3, out_b3, out);
}